// round 5
// baseline (speedup 1.0000x reference)
#include <cuda_runtime.h>
#include <math.h>

// Problem constants
#define NB   16            // batch
#define SQ   256           // sequence
#define MM   768           // model dim
#define TK   10            // stages
#define ROWS (NB*SQ)       // 4096 fused (n, j) rows
#define HID  (4*MM)        // 3072
#define EPS  1e-5f

// ---------------- static scratch (allocation-free rule) ----------------
__device__ float g_s  [ROWS*MM];   // state
__device__ float g_sn [ROWS*MM];   // LN output / t buffer
__device__ float g_v  [ROWS*MM];   // per-stage v
__device__ float g_imv[ROWS*MM];   // exclusive prefix of v
__device__ float g_h  [ROWS*HID];  // MLP hidden
__device__ float g_pe [SQ*MM];     // positional encoding

// ---------------- positional encoding (float64, matches reference) ----
__global__ void pe_kernel(float* __restrict__ pe) {
    int idx = blockIdx.x * 256 + threadIdx.x;
    if (idx >= SQ * MM) return;
    int j = idx / MM;
    int m = idx % MM;
    int z = m & ~1;  // even floor
    double ang = (double)j * exp(-((double)(2 * z) / (double)MM) * log(10000.0));
    pe[idx] = (float)((m & 1) ? cos(ang) : sin(ang));
}

// ---------------- LayerNorm (+optional residual add) ------------------
// one block per row, 256 threads, 3 elements/thread (768 = 3*256)
template <bool ADDRES>
__global__ __launch_bounds__(256) void ln_kernel(
    const float* __restrict__ in, const float* __restrict__ g,
    const float* __restrict__ b, float* __restrict__ out)
{
    int r = blockIdx.x;
    int tid = threadIdx.x;
    const float* row = in + (size_t)r * MM;
    float x0 = row[tid], x1 = row[tid + 256], x2 = row[tid + 512];

    __shared__ float sd[256];
    sd[tid] = x0 + x1 + x2;
    __syncthreads();
    #pragma unroll
    for (int o = 128; o > 0; o >>= 1) {
        if (tid < o) sd[tid] += sd[tid + o];
        __syncthreads();
    }
    float mu = sd[0] * (1.0f / (float)MM);
    __syncthreads();

    float d0 = x0 - mu, d1 = x1 - mu, d2 = x2 - mu;
    sd[tid] = d0 * d0 + d1 * d1 + d2 * d2;
    __syncthreads();
    #pragma unroll
    for (int o = 128; o > 0; o >>= 1) {
        if (tid < o) sd[tid] += sd[tid + o];
        __syncthreads();
    }
    float var  = sd[0] * (1.0f / (float)MM);
    float rstd = 1.0f / sqrtf(var + EPS);

    float* orow = out + (size_t)r * MM;
    orow[tid]       = d0 * rstd * g[tid]       + b[tid]       + (ADDRES ? x0 : 0.f);
    orow[tid + 256] = d1 * rstd * g[tid + 256] + b[tid + 256] + (ADDRES ? x1 : 0.f);
    orow[tid + 512] = d2 * rstd * g[tid + 512] + b[tid + 512] + (ADDRES ? x2 : 0.f);
}

// ---------------- exclusive prefix sum over tokens ---------------------
// chains: (n, d) -> 16*768 = 12288 threads; row stride MM, length SQ.
__global__ __launch_bounds__(256) void scan_kernel(
    const float* __restrict__ v, float* __restrict__ imv)
{
    int idx = blockIdx.x * 256 + threadIdx.x;     // 0..12287
    int n = idx / MM;
    int d = idx % MM;
    const float* src = v   + (size_t)n * SQ * MM + d;
    float*       dst = imv + (size_t)n * SQ * MM + d;
    float acc = 0.f;
    #pragma unroll 8
    for (int j = 0; j < SQ; j++) {
        dst[(size_t)j * MM] = acc;
        acc += src[(size_t)j * MM];
    }
}

// ---------------- tiled SGEMM: C = A(Mr,K) @ W(Nc,K)^T [+ epilogue] ----
// BM=128, BN=64, BK=16, 256 threads, 8x4 per-thread microkernel.
// All dims here are multiples of the tiles (4096 | 768 | 3072), no bounds.
template <bool BIAS, bool RESID, bool GELUF, bool PEB>
__global__ __launch_bounds__(256) void sgemm_tn(
    const float* __restrict__ A, const float* __restrict__ W,
    const float* __restrict__ bias, const float* __restrict__ pe,
    float* __restrict__ C, const float* __restrict__ resid,
    int Mr, int Nc, int K)
{
    constexpr int BM = 128, BN = 64, BK = 16;
    __shared__ float As[BK][BM + 4];
    __shared__ float Bs[BK][BN + 4];

    int tid = threadIdx.x;
    int bx = blockIdx.x;   // column tile
    int by = blockIdx.y;   // row tile
    int tx = tid & 15;     // cols tx*4
    int ty = tid >> 4;     // rows ty*8

    const float* Ab = A + (size_t)(by * BM) * K;
    const float* Wb = W + (size_t)(bx * BN) * K;

    float acc[8][4];
    #pragma unroll
    for (int i = 0; i < 8; i++)
        #pragma unroll
        for (int j = 0; j < 4; j++) acc[i][j] = 0.f;

    for (int kk = 0; kk < K; kk += BK) {
        // --- load A tile: 128x16 = 512 float4, 2 per thread
        #pragma unroll
        for (int L = 0; L < 2; L++) {
            int q   = tid + L * 256;
            int row = q >> 2;
            int kq  = q & 3;
            float4 vA = *(const float4*)(Ab + (size_t)row * K + kk + kq * 4);
            As[kq * 4 + 0][row] = vA.x;
            As[kq * 4 + 1][row] = vA.y;
            As[kq * 4 + 2][row] = vA.z;
            As[kq * 4 + 3][row] = vA.w;
        }
        // --- load W tile: 64x16 = 256 float4, 1 per thread
        {
            int row = tid >> 2;
            int kq  = tid & 3;
            float4 vB = *(const float4*)(Wb + (size_t)row * K + kk + kq * 4);
            Bs[kq * 4 + 0][row] = vB.x;
            Bs[kq * 4 + 1][row] = vB.y;
            Bs[kq * 4 + 2][row] = vB.z;
            Bs[kq * 4 + 3][row] = vB.w;
        }
        __syncthreads();

        #pragma unroll
        for (int k = 0; k < BK; k++) {
            float4 a0 = *(const float4*)&As[k][ty * 8];
            float4 a1 = *(const float4*)&As[k][ty * 8 + 4];
            float4 b0 = *(const float4*)&Bs[k][tx * 4];
            float ar[8] = {a0.x, a0.y, a0.z, a0.w, a1.x, a1.y, a1.z, a1.w};
            float br[4] = {b0.x, b0.y, b0.z, b0.w};
            #pragma unroll
            for (int i = 0; i < 8; i++)
                #pragma unroll
                for (int j = 0; j < 4; j++)
                    acc[i][j] = fmaf(ar[i], br[j], acc[i][j]);
        }
        __syncthreads();
    }

    // --- epilogue
    int c_row0 = by * BM + ty * 8;
    int c_col0 = bx * BN + tx * 4;
    #pragma unroll
    for (int i = 0; i < 8; i++) {
        int r = c_row0 + i;
        float* Crow = C + (size_t)r * Nc + c_col0;
        #pragma unroll
        for (int j = 0; j < 4; j++) {
            float val = acc[i][j];
            if (BIAS)  val += bias[c_col0 + j];
            if (PEB)   val += pe[(size_t)(r & (SQ - 1)) * MM + c_col0 + j];
            if (RESID) val += resid[(size_t)r * Nc + c_col0 + j];
            if (GELUF) val = 0.5f * val * (1.0f + erff(val * 0.70710678118654752f));
            Crow[j] = val;
        }
    }
}

// ---------------- launcher ---------------------------------------------
extern "C" void kernel_launch(void* const* d_in, const int* in_sizes, int n_in,
                              void* d_out, int out_size)
{
    (void)in_sizes; (void)n_in; (void)out_size;
    const float* x      = (const float*)d_in[0];
    const float* weight = (const float*)d_in[1];
    // d_in[2] = Wq, d_in[3] = Wk: provably dead (softmax over size-1 axis == 1)
    const float* Wv     = (const float*)d_in[4];   // (TK,1,768,768)
    const float* Wo     = (const float*)d_in[5];   // (TK,768,768)
    const float* ln1_g  = (const float*)d_in[6];
    const float* ln1_b  = (const float*)d_in[7];
    const float* ln2_g  = (const float*)d_in[8];
    const float* ln2_b  = (const float*)d_in[9];
    const float* fc1_w  = (const float*)d_in[10];  // (3072,768)
    const float* fc1_b  = (const float*)d_in[11];
    const float* fc2_w  = (const float*)d_in[12];  // (768,3072)
    const float* fc2_b  = (const float*)d_in[13];
    float* out = (float*)d_out;

    float *s, *sn, *v, *imv, *h, *pe;
    cudaGetSymbolAddress((void**)&s,   g_s);
    cudaGetSymbolAddress((void**)&sn,  g_sn);
    cudaGetSymbolAddress((void**)&v,   g_v);
    cudaGetSymbolAddress((void**)&imv, g_imv);
    cudaGetSymbolAddress((void**)&h,   g_h);
    cudaGetSymbolAddress((void**)&pe,  g_pe);

    dim3 g768(MM / 64, ROWS / 128);    // (12, 32)
    dim3 g3072(HID / 64, ROWS / 128);  // (48, 32)

    // positional encoding (fp64, once per launch)
    pe_kernel<<<(SQ * MM + 255) / 256, 256>>>(pe);

    // prelude: s = x @ weight^T + PE
    sgemm_tn<false, false, false, true><<<g768, 256>>>(
        x, weight, nullptr, pe, s, nullptr, ROWS, MM, MM);

    // 10 sequential stages, each fully parallel over all (n, j) rows.
    for (int a = 0; a < TK; a++) {
        const float* Wv_a = Wv + (size_t)a * MM * MM;
        const float* Wo_a = Wo + (size_t)a * MM * MM;

        // sn = LN1(s)
        ln_kernel<false><<<ROWS, 256>>>(s, ln1_g, ln1_b, sn);
        // v = sn @ Wv[a]^T
        sgemm_tn<false, false, false, false><<<g768, 256>>>(
            sn, Wv_a, nullptr, nullptr, v, nullptr, ROWS, MM, MM);
        // imv = exclusive cumsum of v over token dim (per batch n)
        scan_kernel<<<(NB * MM) / 256, 256>>>(v, imv);
        // s = imv @ Wo[a]^T + s
        sgemm_tn<false, true, false, false><<<g768, 256>>>(
            imv, Wo_a, nullptr, nullptr, s, s, ROWS, MM, MM);
        // sn(t) = LN2(s) + s
        ln_kernel<true><<<ROWS, 256>>>(s, ln2_g, ln2_b, sn);
        // h = GELU(t @ fc1^T + b1)
        sgemm_tn<true, false, true, false><<<g3072, 256>>>(
            sn, fc1_w, fc1_b, nullptr, h, nullptr, ROWS, HID, MM);
        // s = h @ fc2^T + b2   (last stage writes directly to d_out)
        float* dst = (a == TK - 1) ? out : s;
        sgemm_tn<true, false, false, false><<<g768, 256>>>(
            h, fc2_w, fc2_b, nullptr, dst, nullptr, ROWS, MM, HID);
    }
}